// round 14
// baseline (speedup 1.0000x reference)
#include <cuda_runtime.h>
#include <cuda_bf16.h>
#include <cstdint>

#define NN       2048
#define IN_DIM   256
#define OUT_DIM  512
#define NHEAD    8
#define HDIM     64
#define KSPLIT   8
#define KCHUNK   (NN / KSPLIT)   // 256 keys per split
#define KT       64              // keys per staged tile (attn)
#define QTILE    128
#define QTILES   (NN / QTILE)    // 16

// ---------------- scratch (static device memory; no allocations) -------------
__device__ uint32_t d_Qbf[NHEAD * NN * 32];   // Q bf16x2 scaled, [h][q][d2]
__device__ uint32_t d_Khi[NHEAD * 32 * NN];   // K bf16x2, [h*32+d2][key]
__device__ uint32_t d_xbf[NN * 128];          // x bf16x2, [row][k2]
__device__ uint32_t d_wbf[128 * 1024];        // [Wq|Wk] bf16x2, [k2][col]
__device__ float d_g[NHEAD * NN];             // gate*foldedV, [h][key]
__device__ float d_wv2[IN_DIM * NHEAD];
__device__ float d_bv2[NHEAD];
__device__ float d_accP[KSPLIT][NHEAD * NN];  // [split][h][q]
__device__ float d_lP[KSPLIT][NHEAD * NN];    // [split][h][q]

// ---------------- helpers ----------------------------------------------------
__device__ __forceinline__ float ex2f(float x) {
    float y; asm("ex2.approx.f32 %0, %1;" : "=f"(y) : "f"(x)); return y;
}

__device__ __forceinline__ uint32_t pack2(float x, float y) {
    __nv_bfloat16 hx = __float2bfloat16(x);
    __nv_bfloat16 hy = __float2bfloat16(y);
    return ((uint32_t)__bfloat16_as_ushort(hy) << 16) | (uint32_t)__bfloat16_as_ushort(hx);
}

__device__ __forceinline__ void mma16816(float& c0, float& c1, float& c2, float& c3,
                                         uint32_t a0, uint32_t a1, uint32_t a2, uint32_t a3,
                                         uint32_t b0, uint32_t b1) {
    asm volatile(
        "mma.sync.aligned.m16n8k16.row.col.f32.bf16.bf16.f32 "
        "{%0,%1,%2,%3},{%4,%5,%6,%7},{%8,%9},{%0,%1,%2,%3};"
        : "+f"(c0), "+f"(c1), "+f"(c2), "+f"(c3)
        : "r"(a0), "r"(a1), "r"(a2), "r"(a3), "r"(b0), "r"(b1));
}

__device__ __forceinline__ void cpa16(void* dst, const void* src) {
    uint32_t d = (uint32_t)__cvta_generic_to_shared(dst);
    asm volatile("cp.async.cg.shared.global [%0], [%1], 16;" :: "r"(d), "l"(src));
}
#define CP_COMMIT() asm volatile("cp.async.commit_group;")
#define CP_WAIT1()  asm volatile("cp.async.wait_group 1;")
#define CP_WAIT0()  asm volatile("cp.async.wait_group 0;")

// swizzles: conflict-free fragment loads, 16B-contiguity-preserving stores
#define SWZ(r, c)    (((r) << 6) + ((c) ^ (((r) & 3) << 3)))   // rows of 64 cols
#define SWA(row, k2) ((row) * 8 + ((k2) ^ ((row) & 4)))        // rows of 8 k2

// ---------------- kernel 1: x pack + w pack + Wv-fold fused ------------------
__global__ void prep_all(const float* __restrict__ x,
                         const float* __restrict__ Wq, const float* __restrict__ Wk,
                         const float* __restrict__ Wv, const float* __restrict__ bv,
                         const float* __restrict__ Wo) {
    const int bx = blockIdx.x;
    if (bx < 256) {                      // ---- x pack: [row][k2] ----
        const int u = bx * 256 + threadIdx.x;
        const int row = u >> 5, k2b = (u & 31) * 4;
        float4 v0 = *(const float4*)&x[row * IN_DIM + k2b * 2];
        float4 v1 = *(const float4*)&x[row * IN_DIM + k2b * 2 + 4];
        *(uint4*)&d_xbf[row * 128 + k2b] =
            make_uint4(pack2(v0.x, v0.y), pack2(v0.z, v0.w),
                       pack2(v1.x, v1.y), pack2(v1.z, v1.w));
    } else if (bx < 384) {               // ---- [Wq|Wk] pack: [k2][col] ----
        const int u = (bx - 256) * 256 + threadIdx.x;
        const int k2 = u >> 8, c4 = (u & 255) * 4;
        const float* W = (c4 < 512) ? Wq : Wk;
        const int cc = c4 & 511;
        float4 r0 = *(const float4*)&W[(2 * k2) * OUT_DIM + cc];
        float4 r1 = *(const float4*)&W[(2 * k2 + 1) * OUT_DIM + cc];
        *(uint4*)&d_wbf[k2 * 1024 + c4] =
            make_uint4(pack2(r0.x, r1.x), pack2(r0.y, r1.y),
                       pack2(r0.z, r1.z), pack2(r0.w, r1.w));
    } else {                             // ---- fold Wv,bv through Wo ----
        const int gw = (bx - 384) * 8 + (threadIdx.x >> 5);
        const int lane = threadIdx.x & 31;
        #pragma unroll
        for (int j = 0; j < 4; j++) {
            int p = gw * 4 + j;
            int i = p >> 3, hh = p & 7;
            float s = Wv[i * OUT_DIM + hh * HDIM + lane]      * Wo[hh * HDIM + lane]
                    + Wv[i * OUT_DIM + hh * HDIM + lane + 32] * Wo[hh * HDIM + lane + 32];
            #pragma unroll
            for (int off = 16; off; off >>= 1) s += __shfl_xor_sync(0xffffffffu, s, off);
            if (lane == 0) d_wv2[i * NHEAD + hh] = s;
        }
        if (bx == 384 && threadIdx.x < NHEAD) {
            float s = 0.f;
            #pragma unroll 8
            for (int d = 0; d < HDIM; d++)
                s += bv[threadIdx.x * HDIM + d] * Wo[threadIdx.x * HDIM + d];
            d_bv2[threadIdx.x] = s;
        }
    }
}

// ---------------- kernel 2: QK projection via bf16 MMA -----------------------
// grid (16 mtiles, 16 ntiles), block 256. ntile<8 -> Q (bf16 scaled, [h][q][d2]);
// ntile>=8 -> K (bf16, pre-transposed [h][d2][key]).
__global__ void __launch_bounds__(256, 2)
qkmma_kernel(const float* __restrict__ bq, const float* __restrict__ bk) {
    __shared__ uint32_t sA[2][128 * 8];   // 4 KB per buffer
    __shared__ uint32_t sB[2][8 * 64];    // 2 KB per buffer

    const int tid = threadIdx.x, warp = tid >> 5, lane = tid & 31;
    const int mbase = blockIdx.x * 128, nbase = blockIdx.y * 64;

    float acc[8][4];
    #pragma unroll
    for (int nt = 0; nt < 8; nt++)
        acc[nt][0] = acc[nt][1] = acc[nt][2] = acc[nt][3] = 0.f;

    // staging indices (constant across chunks)
    const int arow = tid >> 1, agrp = (tid & 1) * 4;
    const int adst = SWA(arow, agrp);
    const int bk2 = tid >> 4, bc4 = (tid & 15) * 4;
    const int bdst = bk2 * 64 + (bc4 ^ ((bk2 & 3) << 3));

    // prologue: chunk 0
    {
        cpa16(&sA[0][adst], &d_xbf[(mbase + arow) * 128 + agrp]);
        if (tid < 128) cpa16(&sB[0][bdst], &d_wbf[bk2 * 1024 + nbase + bc4]);
        CP_COMMIT();
    }

    const int r0 = warp * 16 + (lane >> 2), k2l = lane & 3;

    for (int kc = 0; kc < 16; kc++) {
        const int b = kc & 1;
        if (kc < 15) {
            const int nb = b ^ 1, ko = (kc + 1) * 8;
            cpa16(&sA[nb][adst], &d_xbf[(mbase + arow) * 128 + ko + agrp]);
            if (tid < 128) cpa16(&sB[nb][bdst], &d_wbf[(ko + bk2) * 1024 + nbase + bc4]);
            CP_COMMIT();
            CP_WAIT1();
        } else {
            CP_WAIT0();
        }
        __syncthreads();

        const uint32_t a0 = sA[b][SWA(r0,     k2l)];
        const uint32_t a1 = sA[b][SWA(r0 + 8, k2l)];
        const uint32_t a2 = sA[b][SWA(r0,     k2l + 4)];
        const uint32_t a3 = sA[b][SWA(r0 + 8, k2l + 4)];

        #pragma unroll
        for (int nt = 0; nt < 8; nt++) {
            const int col = nt * 8 + (lane >> 2);
            const uint32_t b0 = sB[b][SWZ(k2l,     col)];
            const uint32_t b1 = sB[b][SWZ(k2l + 4, col)];
            mma16816(acc[nt][0], acc[nt][1], acc[nt][2], acc[nt][3],
                     a0, a1, a2, a3, b0, b1);
        }
        __syncthreads();
    }

    // ---- epilogue ----
    const float QSCALE = 1.4426950408889634f / 8.0f;
    const int rg = mbase + warp * 16 + (lane >> 2);
    if (nbase < 512) {        // Q: + bias, scale, bf16 pack, [h][q][d2]
        #pragma unroll
        for (int nt = 0; nt < 8; nt++) {
            const int c = nbase + nt * 8 + (lane & 3) * 2;
            const int h = c >> 6, d2 = (c & 63) >> 1;
            const float b0 = bq[c], b1 = bq[c + 1];
            d_Qbf[(h * NN + rg) * 32 + d2] =
                pack2((acc[nt][0] + b0) * QSCALE, (acc[nt][1] + b1) * QSCALE);
            d_Qbf[(h * NN + rg + 8) * 32 + d2] =
                pack2((acc[nt][2] + b0) * QSCALE, (acc[nt][3] + b1) * QSCALE);
        }
    } else {                  // K: + bias, bf16 pack, transposed [h][d2][key]
        #pragma unroll
        for (int nt = 0; nt < 8; nt++) {
            const int ck = nbase - 512 + nt * 8 + (lane & 3) * 2;
            const float b0 = bk[ck], b1 = bk[ck + 1];
            const int hr = (ck >> 6) * 32 + ((ck & 63) >> 1);
            d_Khi[hr * NN + rg]     = pack2(acc[nt][0] + b0, acc[nt][1] + b1);
            d_Khi[hr * NN + rg + 8] = pack2(acc[nt][2] + b0, acc[nt][3] + b1);
        }
    }
}

// ---------------- kernel 3: motion gate + folded V -> g[h][key] --------------
__global__ void g_kernel(const float* __restrict__ x,
                         const float* __restrict__ rel_vel,
                         const float* __restrict__ rel_angle,
                         const float* __restrict__ Wmg1, const float* __restrict__ bmg1,
                         const float* __restrict__ Wmg2, const float* __restrict__ bmg2) {
    const int warp = threadIdx.x >> 5, lane = threadIdx.x & 31;
    const int row = blockIdx.x * 8 + warp;
    const float rv = rel_vel[row], ra = rel_angle[row];

    const int j0 = lane, j1 = lane + 32;
    float h0 = fmaxf(0.f, fmaf(rv, Wmg1[j0], fmaf(ra, Wmg1[64 + j0], bmg1[j0])));
    float h1 = fmaxf(0.f, fmaf(rv, Wmg1[j1], fmaf(ra, Wmg1[64 + j1], bmg1[j1])));
    float part = fmaf(h0, Wmg2[j0], h1 * Wmg2[j1]);
    #pragma unroll
    for (int off = 16; off; off >>= 1)
        part += __shfl_xor_sync(0xffffffffu, part, off);
    const float mg = 1.f / (1.f + __expf(-(part + bmg2[0])));

    float s[NHEAD];
    #pragma unroll
    for (int h = 0; h < NHEAD; h++) s[h] = 0.f;
    for (int i = lane; i < IN_DIM; i += 32) {
        float xv = x[row * IN_DIM + i];
        #pragma unroll
        for (int h = 0; h < NHEAD; h++)
            s[h] = fmaf(xv, d_wv2[i * NHEAD + h], s[h]);
    }
    #pragma unroll
    for (int off = 16; off; off >>= 1) {
        #pragma unroll
        for (int h = 0; h < NHEAD; h++)
            s[h] += __shfl_xor_sync(0xffffffffu, s[h], off);
    }
    if (lane < NHEAD)
        d_g[lane * NN + row] = mg * (s[lane] + d_bv2[lane]);
}

// ---------------- kernel 4: attention (1-term bf16 MMA, double-buffered) -----
// grid (QTILES, NHEAD, KSPLIT=8), block 256
__global__ void __launch_bounds__(256, 6)
attn_kernel() {
    __shared__ uint32_t sKh[2][32 * 64];   // 8 KB per buffer
    __shared__ float    sg[2][64];

    const int tid  = threadIdx.x;
    const int warp = tid >> 5;
    const int lane = tid & 31;
    const int h      = blockIdx.y;
    const int split  = blockIdx.z;
    const int kbase0 = split * KCHUNK;

    // staging indices (2 uint4 per thread per buffer)
    const int v0 = tid * 2, v1 = tid * 2 + 1;
    const int d2a = v0 >> 4, k4a = (v0 & 15) * 4;
    const int d2b = v1 >> 4, k4b = (v1 & 15) * 4;
    const int dsta = d2a * 64 + (k4a ^ ((d2a & 3) << 3));
    const int dstb = d2b * 64 + (k4b ^ ((d2b & 3) << 3));

    // ---- Q fragments: pre-packed, pre-scaled bf16 from [h][q][d2] ----
    const int qrow = blockIdx.x * QTILE + warp * 16 + (lane >> 2);
    uint32_t aHi[4][4];
    {
        const uint32_t* q0 = &d_Qbf[(h * NN + qrow) * 32];
        const uint32_t* q1 = &d_Qbf[(h * NN + qrow + 8) * 32];
        #pragma unroll
        for (int ks = 0; ks < 4; ks++) {
            const int d2 = ks * 8 + (lane & 3);
            aHi[ks][0] = q0[d2];     aHi[ks][1] = q1[d2];
            aHi[ks][2] = q0[d2 + 4]; aHi[ks][3] = q1[d2 + 4];
        }
    }

    float lsumA = 0.f, lsumB = 0.f, accA = 0.f, accB = 0.f;

    const int T = KCHUNK / KT;   // 4 tiles
    // prologue: tile 0
    {
        const int kb = kbase0;
        cpa16(&sKh[0][dsta], &d_Khi[(h * 32 + d2a) * NN + kb + k4a]);
        cpa16(&sKh[0][dstb], &d_Khi[(h * 32 + d2b) * NN + kb + k4b]);
        if (tid < 16) cpa16(&sg[0][tid * 4], &d_g[h * NN + kb + tid * 4]);
        CP_COMMIT();
    }

    for (int t = 0; t < T; t++) {
        const int b = t & 1;
        if (t < T - 1) {
            const int nb = b ^ 1;
            const int kb = kbase0 + (t + 1) * KT;
            cpa16(&sKh[nb][dsta], &d_Khi[(h * 32 + d2a) * NN + kb + k4a]);
            cpa16(&sKh[nb][dstb], &d_Khi[(h * 32 + d2b) * NN + kb + k4b]);
            if (tid < 16) cpa16(&sg[nb][tid * 4], &d_g[h * NN + kb + tid * 4]);
            CP_COMMIT();
            CP_WAIT1();
        } else {
            CP_WAIT0();
        }
        __syncthreads();

        #pragma unroll
        for (int nt = 0; nt < 8; nt++) {
            float c0 = 0.f, c1 = 0.f, c2 = 0.f, c3 = 0.f;
            const int col = nt * 8 + (lane >> 2);
            #pragma unroll
            for (int ks = 0; ks < 4; ks++) {
                const int r0 = ks * 8 + (lane & 3);
                const uint32_t bh0 = sKh[b][SWZ(r0,     col)];
                const uint32_t bh1 = sKh[b][SWZ(r0 + 4, col)];
                mma16816(c0, c1, c2, c3, aHi[ks][0], aHi[ks][1], aHi[ks][2], aHi[ks][3], bh0, bh1);
            }
            const float g0 = sg[b][nt * 8 + (lane & 3) * 2];
            const float g1 = sg[b][nt * 8 + (lane & 3) * 2 + 1];
            const float p0 = ex2f(c0), p1 = ex2f(c1), p2 = ex2f(c2), p3 = ex2f(c3);
            lsumA += p0 + p1;
            lsumB += p2 + p3;
            accA = fmaf(p0, g0, fmaf(p1, g1, accA));
            accB = fmaf(p2, g0, fmaf(p3, g1, accB));
        }
        __syncthreads();
    }

    #pragma unroll
    for (int off = 1; off <= 2; off <<= 1) {
        lsumA += __shfl_xor_sync(0xffffffffu, lsumA, off);
        lsumB += __shfl_xor_sync(0xffffffffu, lsumB, off);
        accA  += __shfl_xor_sync(0xffffffffu, accA,  off);
        accB  += __shfl_xor_sync(0xffffffffu, accB,  off);
    }
    if ((lane & 3) == 0) {
        d_lP[split][h * NN + qrow]           = lsumA;
        d_accP[split][h * NN + qrow]         = accA;
        d_lP[split][h * NN + qrow + 8]       = lsumB;
        d_accP[split][h * NN + qrow + 8]     = accB;
    }
}

// ---------------- kernel 5: combine splits, divide, sum heads ----------------
// grid 64, block 256: warp = head, lane = query within 32-query chunk
__global__ void final_kernel(float* __restrict__ out, const float* __restrict__ bo) {
    __shared__ float sr[NHEAD][32];
    const int lane = threadIdx.x & 31, h = threadIdx.x >> 5;
    const int q = blockIdx.x * 32 + lane;

    float a = 0.f, l = 0.f;
    #pragma unroll
    for (int s = 0; s < KSPLIT; s++) {
        a += d_accP[s][h * NN + q];
        l += d_lP[s][h * NN + q];
    }
    sr[h][lane] = a / l;
    __syncthreads();
    if (h == 0) {
        float o = bo[0];
        #pragma unroll
        for (int hh = 0; hh < NHEAD; hh++) o += sr[hh][lane];
        out[q] = o;
    }
}

// ---------------- launch ------------------------------------------------------
extern "C" void kernel_launch(void* const* d_in, const int* in_sizes, int n_in,
                              void* d_out, int out_size) {
    const float* x         = (const float*)d_in[0];
    // d_in[1] = rel_pos (unused: spatial bias is constant along softmax axis)
    const float* rel_vel   = (const float*)d_in[2];
    const float* rel_angle = (const float*)d_in[3];
    const float* Wq = (const float*)d_in[4];
    const float* bq = (const float*)d_in[5];
    const float* Wk = (const float*)d_in[6];
    const float* bk = (const float*)d_in[7];
    const float* Wv = (const float*)d_in[8];
    const float* bv = (const float*)d_in[9];
    // d_in[10..13] = Wsb1,bsb1,Wsb2,bsb2 (unused)
    const float* Wmg1 = (const float*)d_in[14];
    const float* bmg1 = (const float*)d_in[15];
    const float* Wmg2 = (const float*)d_in[16];
    const float* bmg2 = (const float*)d_in[17];
    const float* Wo   = (const float*)d_in[18];
    const float* bo   = (const float*)d_in[19];
    float* out = (float*)d_out;

    prep_all<<<448, 256>>>(x, Wq, Wk, Wv, bv, Wo);
    qkmma_kernel<<<dim3(16, 16), 256>>>(bq, bk);
    g_kernel<<<NN / 8, 256>>>(x, rel_vel, rel_angle, Wmg1, bmg1, Wmg2, bmg2);
    attn_kernel<<<dim3(QTILES, NHEAD, KSPLIT), 256>>>();
    final_kernel<<<NN / 32, 256>>>(out, bo);
}

// round 15
// speedup vs baseline: 1.2455x; 1.2455x over previous
#include <cuda_runtime.h>
#include <cuda_bf16.h>
#include <cstdint>

#define NN       2048
#define IN_DIM   256
#define OUT_DIM  512
#define NHEAD    8
#define HDIM     64
#define KSPLIT   4
#define KCHUNK   (NN / KSPLIT)   // 512 keys per split
#define KT       64              // keys per staged tile (attn)
#define QTILE    128
#define QTILES   (NN / QTILE)    // 16

// ---------------- scratch (static device memory; no allocations) -------------
__device__ uint32_t d_Qbf[NHEAD * NN * 32];   // Q bf16x2 scaled, [h][q][d2]
__device__ uint32_t d_K[NHEAD * NN * 32];     // K bf16x2, [h][key][pair e: (d2,d2+4)]
__device__ uint32_t d_xbf[NN * 128];          // x bf16x2, [row][k2]
__device__ uint32_t d_wbf[128 * 1024];        // [Wq|Wk] bf16x2, [k2][col]
__device__ float d_g[NHEAD * NN];             // gate*foldedV, [h][key]
__device__ float d_wv2[IN_DIM * NHEAD];
__device__ float d_bv2[NHEAD];
__device__ float d_accP[KSPLIT][NHEAD * NN];  // [split][h][q]
__device__ float d_lP[KSPLIT][NHEAD * NN];    // [split][h][q]

// ---------------- helpers ----------------------------------------------------
__device__ __forceinline__ float ex2f(float x) {
    float y; asm("ex2.approx.f32 %0, %1;" : "=f"(y) : "f"(x)); return y;
}

__device__ __forceinline__ uint32_t pack2(float x, float y) {
    __nv_bfloat16 hx = __float2bfloat16(x);
    __nv_bfloat16 hy = __float2bfloat16(y);
    return ((uint32_t)__bfloat16_as_ushort(hy) << 16) | (uint32_t)__bfloat16_as_ushort(hx);
}

__device__ __forceinline__ void mma16816(float& c0, float& c1, float& c2, float& c3,
                                         uint32_t a0, uint32_t a1, uint32_t a2, uint32_t a3,
                                         uint32_t b0, uint32_t b1) {
    asm volatile(
        "mma.sync.aligned.m16n8k16.row.col.f32.bf16.bf16.f32 "
        "{%0,%1,%2,%3},{%4,%5,%6,%7},{%8,%9},{%0,%1,%2,%3};"
        : "+f"(c0), "+f"(c1), "+f"(c2), "+f"(c3)
        : "r"(a0), "r"(a1), "r"(a2), "r"(a3), "r"(b0), "r"(b1));
}

__device__ __forceinline__ void cpa16(void* dst, const void* src) {
    uint32_t d = (uint32_t)__cvta_generic_to_shared(dst);
    asm volatile("cp.async.cg.shared.global [%0], [%1], 16;" :: "r"(d), "l"(src));
}
#define CP_COMMIT() asm volatile("cp.async.commit_group;")
#define CP_WAIT1()  asm volatile("cp.async.wait_group 1;")
#define CP_WAIT0()  asm volatile("cp.async.wait_group 0;")

// swizzles for qkmma (unchanged)
#define SWZ(r, c)    (((r) << 6) + ((c) ^ (((r) & 3) << 3)))   // rows of 64 cols
#define SWA(row, k2) ((row) * 8 + ((k2) ^ ((row) & 4)))        // rows of 8 k2

// ---------------- kernel 1: x pack + w pack + Wv-fold fused ------------------
__global__ void prep_all(const float* __restrict__ x,
                         const float* __restrict__ Wq, const float* __restrict__ Wk,
                         const float* __restrict__ Wv, const float* __restrict__ bv,
                         const float* __restrict__ Wo) {
    const int bx = blockIdx.x;
    if (bx < 256) {                      // ---- x pack: [row][k2] ----
        const int u = bx * 256 + threadIdx.x;
        const int row = u >> 5, k2b = (u & 31) * 4;
        float4 v0 = *(const float4*)&x[row * IN_DIM + k2b * 2];
        float4 v1 = *(const float4*)&x[row * IN_DIM + k2b * 2 + 4];
        *(uint4*)&d_xbf[row * 128 + k2b] =
            make_uint4(pack2(v0.x, v0.y), pack2(v0.z, v0.w),
                       pack2(v1.x, v1.y), pack2(v1.z, v1.w));
    } else if (bx < 384) {               // ---- [Wq|Wk] pack: [k2][col] ----
        const int u = (bx - 256) * 256 + threadIdx.x;
        const int k2 = u >> 8, c4 = (u & 255) * 4;
        const float* W = (c4 < 512) ? Wq : Wk;
        const int cc = c4 & 511;
        float4 r0 = *(const float4*)&W[(2 * k2) * OUT_DIM + cc];
        float4 r1 = *(const float4*)&W[(2 * k2 + 1) * OUT_DIM + cc];
        *(uint4*)&d_wbf[k2 * 1024 + c4] =
            make_uint4(pack2(r0.x, r1.x), pack2(r0.y, r1.y),
                       pack2(r0.z, r1.z), pack2(r0.w, r1.w));
    } else {                             // ---- fold Wv,bv through Wo ----
        const int gw = (bx - 384) * 8 + (threadIdx.x >> 5);
        const int lane = threadIdx.x & 31;
        #pragma unroll
        for (int j = 0; j < 4; j++) {
            int p = gw * 4 + j;
            int i = p >> 3, hh = p & 7;
            float s = Wv[i * OUT_DIM + hh * HDIM + lane]      * Wo[hh * HDIM + lane]
                    + Wv[i * OUT_DIM + hh * HDIM + lane + 32] * Wo[hh * HDIM + lane + 32];
            #pragma unroll
            for (int off = 16; off; off >>= 1) s += __shfl_xor_sync(0xffffffffu, s, off);
            if (lane == 0) d_wv2[i * NHEAD + hh] = s;
        }
        if (bx == 384 && threadIdx.x < NHEAD) {
            float s = 0.f;
            #pragma unroll 8
            for (int d = 0; d < HDIM; d++)
                s += bv[threadIdx.x * HDIM + d] * Wo[threadIdx.x * HDIM + d];
            d_bv2[threadIdx.x] = s;
        }
    }
}

// ---------------- kernel 2: QK projection via bf16 MMA -----------------------
// grid (16 mtiles, 16 ntiles), block 256. ntile<8 -> Q (bf16 scaled, [h][q][d2]);
// ntile>=8 -> K (bf16, key-major [h][key][pair]).
__global__ void __launch_bounds__(256, 2)
qkmma_kernel(const float* __restrict__ bq, const float* __restrict__ bk) {
    __shared__ uint32_t sA[2][128 * 8];   // 4 KB per buffer
    __shared__ uint32_t sB[2][8 * 64];    // 2 KB per buffer

    const int tid = threadIdx.x, warp = tid >> 5, lane = tid & 31;
    const int mbase = blockIdx.x * 128, nbase = blockIdx.y * 64;

    float acc[8][4];
    #pragma unroll
    for (int nt = 0; nt < 8; nt++)
        acc[nt][0] = acc[nt][1] = acc[nt][2] = acc[nt][3] = 0.f;

    // staging indices (constant across chunks)
    const int arow = tid >> 1, agrp = (tid & 1) * 4;
    const int adst = SWA(arow, agrp);
    const int bk2 = tid >> 4, bc4 = (tid & 15) * 4;
    const int bdst = bk2 * 64 + (bc4 ^ ((bk2 & 3) << 3));

    // prologue: chunk 0
    {
        cpa16(&sA[0][adst], &d_xbf[(mbase + arow) * 128 + agrp]);
        if (tid < 128) cpa16(&sB[0][bdst], &d_wbf[bk2 * 1024 + nbase + bc4]);
        CP_COMMIT();
    }

    const int r0 = warp * 16 + (lane >> 2), k2l = lane & 3;

    for (int kc = 0; kc < 16; kc++) {
        const int b = kc & 1;
        if (kc < 15) {
            const int nb = b ^ 1, ko = (kc + 1) * 8;
            cpa16(&sA[nb][adst], &d_xbf[(mbase + arow) * 128 + ko + agrp]);
            if (tid < 128) cpa16(&sB[nb][bdst], &d_wbf[(ko + bk2) * 1024 + nbase + bc4]);
            CP_COMMIT();
            CP_WAIT1();
        } else {
            CP_WAIT0();
        }
        __syncthreads();

        const uint32_t a0 = sA[b][SWA(r0,     k2l)];
        const uint32_t a1 = sA[b][SWA(r0 + 8, k2l)];
        const uint32_t a2 = sA[b][SWA(r0,     k2l + 4)];
        const uint32_t a3 = sA[b][SWA(r0 + 8, k2l + 4)];

        #pragma unroll
        for (int nt = 0; nt < 8; nt++) {
            const int col = nt * 8 + (lane >> 2);
            const uint32_t b0 = sB[b][SWZ(k2l,     col)];
            const uint32_t b1 = sB[b][SWZ(k2l + 4, col)];
            mma16816(acc[nt][0], acc[nt][1], acc[nt][2], acc[nt][3],
                     a0, a1, a2, a3, b0, b1);
        }
        __syncthreads();
    }

    // ---- epilogue ----
    const float QSCALE = 1.4426950408889634f / 8.0f;
    const int rg = mbase + warp * 16 + (lane >> 2);
    if (nbase < 512) {        // Q: + bias, scale, bf16 pack, [h][q][d2]
        #pragma unroll
        for (int nt = 0; nt < 8; nt++) {
            const int c = nbase + nt * 8 + (lane & 3) * 2;
            const int h = c >> 6, d2 = (c & 63) >> 1;
            const float b0 = bq[c], b1 = bq[c + 1];
            d_Qbf[(h * NN + rg) * 32 + d2] =
                pack2((acc[nt][0] + b0) * QSCALE, (acc[nt][1] + b1) * QSCALE);
            d_Qbf[(h * NN + rg + 8) * 32 + d2] =
                pack2((acc[nt][2] + b0) * QSCALE, (acc[nt][3] + b1) * QSCALE);
        }
    } else {                  // K: + bias, bf16 pack, key-major [h][key][pair]
        #pragma unroll
        for (int nt = 0; nt < 8; nt++) {
            const int ck = nbase - 512 + nt * 8 + (lane & 3) * 2;
            const float b0 = bk[ck], b1 = bk[ck + 1];
            const int hh = ck >> 6, d2 = (ck & 63) >> 1;
            // pair e = (d2>>3)*4 + (d2&3) holds (d2, d2+4); lo selects member
            const int idx = (((d2 >> 3) * 4 + (d2 & 3)) << 1) | ((d2 >> 2) & 1);
            d_K[(hh * NN + rg) * 32 + idx]     = pack2(acc[nt][0] + b0, acc[nt][1] + b1);
            d_K[(hh * NN + rg + 8) * 32 + idx] = pack2(acc[nt][2] + b0, acc[nt][3] + b1);
        }
    }
}

// ---------------- kernel 3: motion gate + folded V -> g[h][key] --------------
__global__ void g_kernel(const float* __restrict__ x,
                         const float* __restrict__ rel_vel,
                         const float* __restrict__ rel_angle,
                         const float* __restrict__ Wmg1, const float* __restrict__ bmg1,
                         const float* __restrict__ Wmg2, const float* __restrict__ bmg2) {
    const int warp = threadIdx.x >> 5, lane = threadIdx.x & 31;
    const int row = blockIdx.x * 8 + warp;
    const float rv = rel_vel[row], ra = rel_angle[row];

    const int j0 = lane, j1 = lane + 32;
    float h0 = fmaxf(0.f, fmaf(rv, Wmg1[j0], fmaf(ra, Wmg1[64 + j0], bmg1[j0])));
    float h1 = fmaxf(0.f, fmaf(rv, Wmg1[j1], fmaf(ra, Wmg1[64 + j1], bmg1[j1])));
    float part = fmaf(h0, Wmg2[j0], h1 * Wmg2[j1]);
    #pragma unroll
    for (int off = 16; off; off >>= 1)
        part += __shfl_xor_sync(0xffffffffu, part, off);
    const float mg = 1.f / (1.f + __expf(-(part + bmg2[0])));

    float s[NHEAD];
    #pragma unroll
    for (int h = 0; h < NHEAD; h++) s[h] = 0.f;
    for (int i = lane; i < IN_DIM; i += 32) {
        float xv = x[row * IN_DIM + i];
        #pragma unroll
        for (int h = 0; h < NHEAD; h++)
            s[h] = fmaf(xv, d_wv2[i * NHEAD + h], s[h]);
    }
    #pragma unroll
    for (int off = 16; off; off >>= 1) {
        #pragma unroll
        for (int h = 0; h < NHEAD; h++)
            s[h] += __shfl_xor_sync(0xffffffffu, s[h], off);
    }
    if (lane < NHEAD)
        d_g[lane * NN + row] = mg * (s[lane] + d_bv2[lane]);
}

// ---------------- kernel 4: attention (LDS.64 B-frags, double-buffered) ------
// grid (QTILES, NHEAD, KSPLIT), block 256
__global__ void __launch_bounds__(256, 6)
attn_kernel() {
    __shared__ uint32_t sK[2][64 * 32];   // 8 KB per buffer: [key][pair swizzled]
    __shared__ float    sg[2][64];

    const int tid  = threadIdx.x;
    const int warp = tid >> 5;
    const int lane = tid & 31;
    const int j2   = lane & 3;
    const int q4   = lane >> 2;
    const int h      = blockIdx.y;
    const int split  = blockIdx.z;
    const int kbase0 = split * KCHUNK;

    // staging: 2 chunks of 16B per thread; chunk c -> key = c>>3, cg = c&7
    const int ky0 = (tid * 2) >> 3,     cg0 = (tid * 2) & 7;
    const int ky1 = (tid * 2 + 1) >> 3, cg1 = (tid * 2 + 1) & 7;
    const int kdst0 = ky0 * 32 + ((cg0 * 4) ^ ((ky0 & 3) << 3));
    const int kdst1 = ky1 * 32 + ((cg1 * 4) ^ ((ky1 & 3) << 3));

    // ---- Q fragments: pre-packed, pre-scaled bf16 from [h][q][d2] ----
    const int qrow = blockIdx.x * QTILE + warp * 16 + q4;
    uint32_t aHi[4][4];
    {
        const uint32_t* q0 = &d_Qbf[(h * NN + qrow) * 32];
        const uint32_t* q1 = &d_Qbf[(h * NN + qrow + 8) * 32];
        #pragma unroll
        for (int ks = 0; ks < 4; ks++) {
            const int d2 = ks * 8 + j2;
            aHi[ks][0] = q0[d2];     aHi[ks][1] = q1[d2];
            aHi[ks][2] = q0[d2 + 4]; aHi[ks][3] = q1[d2 + 4];
        }
    }
    const int psw = (q4 & 3) << 2;   // pair-index XOR for this thread's key row

    float lsumA = 0.f, lsumB = 0.f, accA = 0.f, accB = 0.f;

    const int T = KCHUNK / KT;   // 8 tiles
    // prologue: tile 0
    {
        const int kb = kbase0;
        cpa16(&sK[0][kdst0], &d_K[(h * NN + kb + ky0) * 32 + cg0 * 4]);
        cpa16(&sK[0][kdst1], &d_K[(h * NN + kb + ky1) * 32 + cg1 * 4]);
        if (tid < 16) cpa16(&sg[0][tid * 4], &d_g[h * NN + kb + tid * 4]);
        CP_COMMIT();
    }

    for (int t = 0; t < T; t++) {
        const int b = t & 1;
        if (t < T - 1) {
            const int nb = b ^ 1;
            const int kb = kbase0 + (t + 1) * KT;
            cpa16(&sK[nb][kdst0], &d_K[(h * NN + kb + ky0) * 32 + cg0 * 4]);
            cpa16(&sK[nb][kdst1], &d_K[(h * NN + kb + ky1) * 32 + cg1 * 4]);
            if (tid < 16) cpa16(&sg[nb][tid * 4], &d_g[h * NN + kb + tid * 4]);
            CP_COMMIT();
            CP_WAIT1();
        } else {
            CP_WAIT0();
        }
        __syncthreads();

        #pragma unroll
        for (int nt = 0; nt < 8; nt++) {
            float c0 = 0.f, c1 = 0.f, c2 = 0.f, c3 = 0.f;
            const uint32_t* krow = &sK[b][(nt * 8 + q4) * 32];
            #pragma unroll
            for (int ks = 0; ks < 4; ks++) {
                const uint2 p = *(const uint2*)&krow[((ks * 4 + j2) ^ psw) << 1];
                mma16816(c0, c1, c2, c3,
                         aHi[ks][0], aHi[ks][1], aHi[ks][2], aHi[ks][3], p.x, p.y);
            }
            const float g0 = sg[b][nt * 8 + j2 * 2];
            const float g1 = sg[b][nt * 8 + j2 * 2 + 1];
            const float p0 = ex2f(c0), p1 = ex2f(c1), p2 = ex2f(c2), p3 = ex2f(c3);
            lsumA += p0 + p1;
            lsumB += p2 + p3;
            accA = fmaf(p0, g0, fmaf(p1, g1, accA));
            accB = fmaf(p2, g0, fmaf(p3, g1, accB));
        }
        __syncthreads();
    }

    #pragma unroll
    for (int off = 1; off <= 2; off <<= 1) {
        lsumA += __shfl_xor_sync(0xffffffffu, lsumA, off);
        lsumB += __shfl_xor_sync(0xffffffffu, lsumB, off);
        accA  += __shfl_xor_sync(0xffffffffu, accA,  off);
        accB  += __shfl_xor_sync(0xffffffffu, accB,  off);
    }
    if (j2 == 0) {
        d_lP[split][h * NN + qrow]       = lsumA;
        d_accP[split][h * NN + qrow]     = accA;
        d_lP[split][h * NN + qrow + 8]   = lsumB;
        d_accP[split][h * NN + qrow + 8] = accB;
    }
}

// ---------------- kernel 5: combine splits, divide, sum heads ----------------
// grid 64, block 256: warp = head, lane = query within 32-query chunk
__global__ void final_kernel(float* __restrict__ out, const float* __restrict__ bo) {
    __shared__ float sr[NHEAD][32];
    const int lane = threadIdx.x & 31, h = threadIdx.x >> 5;
    const int q = blockIdx.x * 32 + lane;

    float a = 0.f, l = 0.f;
    #pragma unroll
    for (int s = 0; s < KSPLIT; s++) {
        a += d_accP[s][h * NN + q];
        l += d_lP[s][h * NN + q];
    }
    sr[h][lane] = a / l;
    __syncthreads();
    if (h == 0) {
        float o = bo[0];
        #pragma unroll
        for (int hh = 0; hh < NHEAD; hh++) o += sr[hh][lane];
        out[q] = o;
    }
}

// ---------------- launch ------------------------------------------------------
extern "C" void kernel_launch(void* const* d_in, const int* in_sizes, int n_in,
                              void* d_out, int out_size) {
    const float* x         = (const float*)d_in[0];
    // d_in[1] = rel_pos (unused: spatial bias is constant along softmax axis)
    const float* rel_vel   = (const float*)d_in[2];
    const float* rel_angle = (const float*)d_in[3];
    const float* Wq = (const float*)d_in[4];
    const float* bq = (const float*)d_in[5];
    const float* Wk = (const float*)d_in[6];
    const float* bk = (const float*)d_in[7];
    const float* Wv = (const float*)d_in[8];
    const float* bv = (const float*)d_in[9];
    // d_in[10..13] = Wsb1,bsb1,Wsb2,bsb2 (unused)
    const float* Wmg1 = (const float*)d_in[14];
    const float* bmg1 = (const float*)d_in[15];
    const float* Wmg2 = (const float*)d_in[16];
    const float* bmg2 = (const float*)d_in[17];
    const float* Wo   = (const float*)d_in[18];
    const float* bo   = (const float*)d_in[19];
    float* out = (float*)d_out;

    prep_all<<<448, 256>>>(x, Wq, Wk, Wv, bv, Wo);
    qkmma_kernel<<<dim3(16, 16), 256>>>(bq, bk);
    g_kernel<<<NN / 8, 256>>>(x, rel_vel, rel_angle, Wmg1, bmg1, Wmg2, bmg2);
    attn_kernel<<<dim3(QTILES, NHEAD, KSPLIT), 256>>>();
    final_kernel<<<NN / 32, 256>>>(out, bo);
}